// round 10
// baseline (speedup 1.0000x reference)
#include <cuda_runtime.h>
#include <math.h>

#define BB   64
#define TT   512
#define NIN  256
#define NH   2048
#define NOUT 256
#define NCTA 128   // 16 n-tiles x 8 k-splits, all co-resident
#define KS   8     // K splits
#define NT   16    // n tiles (128 cols each)

typedef unsigned long long ull;

// Scratch (device globals; no allocation anywhere)
__device__ float g_X[(size_t)BB * TT * NH];        // [b*T+t][NH]
__device__ float g_H[(size_t)(TT + 1) * BB * NH];  // [t][b][NH]
__device__ float g_P[(size_t)KS * BB * NH];        // [ks][b][NH]
__device__ volatile unsigned g_flags[NCTA];
__device__ volatile unsigned g_rel;

// Packed fp32x2 helpers (sm_103a FFMA2 — only reachable via PTX)
__device__ __forceinline__ ull bcast2(float x) {
    ull r;
    asm("mov.b64 %0, {%1, %1};" : "=l"(r) : "f"(x));
    return r;
}
__device__ __forceinline__ void ffma2(ull& d, ull a, ull b) {
    asm("fma.rn.f32x2 %0, %1, %2, %0;" : "+l"(d) : "l"(a), "l"(b));
}

// ---------------------------------------------------------------------------
// GEMM1: g_X = u @ W_uh + b_h     (M=32768, K=256, N=2048), 128x128 tile
// ---------------------------------------------------------------------------
__global__ __launch_bounds__(256) void gemm1_kernel(const float* __restrict__ u,
                                                    const float* __restrict__ W,
                                                    const float* __restrict__ bias) {
    __shared__ float sA[16][129];
    __shared__ float sB[16][128];
    const int m0 = blockIdx.x * 128;
    const int n0 = blockIdx.y * 128;
    const int tid = threadIdx.x;
    const int tcol = tid & 15;
    const int trow = tid >> 4;
    ull acc2[8][4];
#pragma unroll
    for (int i = 0; i < 8; i++)
#pragma unroll
        for (int j = 0; j < 4; j++) acc2[i][j] = 0ull;

    for (int k0 = 0; k0 < NIN; k0 += 16) {
#pragma unroll
        for (int i = 0; i < 8; i++) {
            int idx = tid + i * 256;
            int m = idx >> 4, k = idx & 15;
            sA[k][m] = u[(size_t)(m0 + m) * NIN + k0 + k];
        }
#pragma unroll
        for (int i = 0; i < 8; i++) {
            int idx = tid + i * 256;
            int k = idx >> 7, n = idx & 127;
            sB[k][n] = W[(size_t)(k0 + k) * NH + n0 + n];
        }
        __syncthreads();
#pragma unroll
        for (int kk = 0; kk < 16; kk++) {
            const ulonglong2* bp = (const ulonglong2*)(&sB[kk][tcol * 8]);
            ulonglong2 B0 = bp[0], B1 = bp[1];
            ull bv2[4] = {B0.x, B0.y, B1.x, B1.y};
#pragma unroll
            for (int i = 0; i < 8; i++) {
                ull a2 = bcast2(sA[kk][trow * 8 + i]);
#pragma unroll
                for (int j = 0; j < 4; j++) ffma2(acc2[i][j], a2, bv2[j]);
            }
        }
        __syncthreads();
    }
#pragma unroll
    for (int i = 0; i < 8; i++) {
        int m = m0 + trow * 8 + i;
#pragma unroll
        for (int j = 0; j < 4; j++) {
            int n = n0 + tcol * 8 + 2 * j;
            float2 v = *(float2*)&acc2[i][j];
            g_X[(size_t)m * NH + n] = v.x + bias[n];
            g_X[(size_t)m * NH + n + 1] = v.y + bias[n + 1];
        }
    }
}

// ---------------------------------------------------------------------------
// Flag-based grid barrier: per-CTA arrival slots (no same-address atomics),
// CTA 0 gathers with 128 parallel spinners, releases via one word.
// gen is a per-thread monotonic counter seeded from g_rel at kernel start.
// ---------------------------------------------------------------------------
__device__ __forceinline__ void grid_bar(unsigned& gen, int cid, int tid) {
    gen++;
    __syncthreads();
    __threadfence();
    if (tid == 0) g_flags[cid] = gen;
    if (cid == 0) {
        if (tid < NCTA) {
            while (g_flags[tid] < gen) { }
        }
        __syncthreads();
        if (tid == 0) {
            __threadfence();
            g_rel = gen;
        }
    }
    if (tid == 0) {
        while (g_rel < gen) { }
    }
    __syncthreads();
}

// ---------------------------------------------------------------------------
// Persistent recurrence: one launch, 512 steps.
// CTA (nt, ks): phase A computes partial pre[64b x 128n] over K-slice
// [ks*256, ks*256+256), with its Whh slice resident in smem (n-contiguous
// rows for packed-pair loads). One flag-barrier, then phase B fixed-order
// reduce over 8 splits + leaky tanh, second barrier.
// ---------------------------------------------------------------------------
__global__ __launch_bounds__(256, 1) void recur_kernel(const float* __restrict__ Whh,
                                                       const float* __restrict__ tau,
                                                       const float* __restrict__ h0) {
    extern __shared__ float smem[];
    float* sW = smem;                    // [256 k][128 n]  (131072 B)
    float* sH = smem + 256 * 128;        // [64 b][260]     (66560 B)
    const int HS = 260;                  // sH row stride (floats)

    const int tid = threadIdx.x;
    const int cid = blockIdx.x;
    const int nt = cid & (NT - 1);
    const int ks = cid >> 4;
    const int n0 = nt * 128;
    const int kb = ks * 256;
    const int tcol = tid & 15;           // n-group of 8
    const int trow = tid >> 4;           // b-group of 4

    unsigned gen = g_rel;                // resume monotonic generation

    // Preload Whh slice [kb..kb+256) x [n0..n0+128) into smem (reused 512x)
    for (int i = tid; i < 256 * 32; i += 256) {   // 8192 float4
        int k = i >> 5, n4 = i & 31;
        ((float4*)(sW + k * 128))[n4] =
            ((const float4*)(Whh + (size_t)(kb + k) * NH + n0))[n4];
    }

    // Init g_H[0]: elems [cid*1024, cid*1024+1024)
    {
        int base = cid * 1024 + tid * 4;
        int j = base & (NH - 1);
        float4 v = *(const float4*)(h0 + j);
        v.x = fminf(1.f, fmaxf(-1.f, v.x));
        v.y = fminf(1.f, fmaxf(-1.f, v.y));
        v.z = fminf(1.f, fmaxf(-1.f, v.z));
        v.w = fminf(1.f, fmaxf(-1.f, v.w));
        *(float4*)(g_H + base) = v;
    }
    grid_bar(gen, cid, tid);

    float* __restrict__ Pp = g_P + (size_t)ks * BB * NH;
    const int fbase = cid * 1024 + tid * 4;
    const int fb = fbase >> 11;
    const int fj = fbase & (NH - 1);
    const float4 tv = *(const float4*)(tau + fj);
    float4 av4;
    av4.x = 1.0f / tv.x; av4.y = 1.0f / tv.y; av4.z = 1.0f / tv.z; av4.w = 1.0f / tv.w;

    for (int t = 0; t < TT; t++) {
        // ---- Phase A: partial GEMM (packed f32x2, n-paired) ----
        const float* __restrict__ Ht = g_H + (size_t)t * BB * NH;
        for (int i = tid; i < 64 * 64; i += 256) {   // 4096 float4: sH[b][k]
            int b = i >> 6, k4 = i & 63;
            *(float4*)(sH + b * HS + k4 * 4) =
                *(const float4*)(Ht + (size_t)b * NH + kb + k4 * 4);
        }
        __syncthreads();

        ull acc2[4][4];
#pragma unroll
        for (int i = 0; i < 4; i++)
#pragma unroll
            for (int j = 0; j < 4; j++) acc2[i][j] = 0ull;

#pragma unroll 4
        for (int kk = 0; kk < 256; kk++) {
            const ulonglong2* wp = (const ulonglong2*)(sW + kk * 128 + tcol * 8);
            ulonglong2 W0 = wp[0], W1 = wp[1];
            ull wv2[4] = {W0.x, W0.y, W1.x, W1.y};
#pragma unroll
            for (int i = 0; i < 4; i++) {
                ull h2 = bcast2(sH[(trow * 4 + i) * HS + kk]);
#pragma unroll
                for (int j = 0; j < 4; j++) ffma2(acc2[i][j], h2, wv2[j]);
            }
        }

#pragma unroll
        for (int i = 0; i < 4; i++) {
            int b = trow * 4 + i;
            ulonglong2* dst = (ulonglong2*)(Pp + (size_t)b * NH + n0 + tcol * 8);
            dst[0] = make_ulonglong2(acc2[i][0], acc2[i][1]);
            dst[1] = make_ulonglong2(acc2[i][2], acc2[i][3]);
        }
        grid_bar(gen, cid, tid);

        // ---- Phase B: fixed-order reduce over 8 splits + leaky tanh ----
        float4 pre = *(const float4*)(g_X + ((size_t)fb * TT + t) * NH + fj);
#pragma unroll
        for (int s = 0; s < KS; s++) {
            float4 p = __ldcg((const float4*)(g_P + (size_t)s * BB * NH + fbase));
            pre.x += p.x; pre.y += p.y; pre.z += p.z; pre.w += p.w;
        }
        float4 h = *(const float4*)(g_H + (size_t)t * BB * NH + fbase);
        float4 hn;
        hn.x = (1.0f - av4.x) * h.x + av4.x * tanhf(pre.x);
        hn.y = (1.0f - av4.y) * h.y + av4.y * tanhf(pre.y);
        hn.z = (1.0f - av4.z) * h.z + av4.z * tanhf(pre.z);
        hn.w = (1.0f - av4.w) * h.w + av4.w * tanhf(pre.w);
        *(float4*)(g_H + (size_t)(t + 1) * BB * NH + fbase) = hn;
        grid_bar(gen, cid, tid);
    }
}

// ---------------------------------------------------------------------------
// GEMM3: logits = H[t+1] @ W_hy + b_y  (M=32768, K=2048, N=256)
// ---------------------------------------------------------------------------
__global__ __launch_bounds__(256) void gemm3_kernel(const float* __restrict__ Why,
                                                    const float* __restrict__ by,
                                                    float* __restrict__ out) {
    __shared__ float sA[16][129];
    __shared__ float sB[16][128];
    const int m0 = blockIdx.x * 128;
    const int n0 = blockIdx.y * 128;
    const int tid = threadIdx.x;
    const int tcol = tid & 15;
    const int trow = tid >> 4;
    ull acc2[8][4];
#pragma unroll
    for (int i = 0; i < 8; i++)
#pragma unroll
        for (int j = 0; j < 4; j++) acc2[i][j] = 0ull;

    for (int k0 = 0; k0 < NH; k0 += 16) {
#pragma unroll
        for (int i = 0; i < 8; i++) {
            int idx = tid + i * 256;
            int m = idx >> 4, k = idx & 15;
            int gm = m0 + m;
            int b = gm >> 9;
            int tt = gm & (TT - 1);
            sA[k][m] = g_H[((size_t)(tt + 1) * BB + b) * NH + k0 + k];
        }
#pragma unroll
        for (int i = 0; i < 8; i++) {
            int idx = tid + i * 256;
            int k = idx >> 7, n = idx & 127;
            sB[k][n] = Why[(size_t)(k0 + k) * NOUT + n0 + n];
        }
        __syncthreads();
#pragma unroll
        for (int kk = 0; kk < 16; kk++) {
            const ulonglong2* bp = (const ulonglong2*)(&sB[kk][tcol * 8]);
            ulonglong2 B0 = bp[0], B1 = bp[1];
            ull bv2[4] = {B0.x, B0.y, B1.x, B1.y};
#pragma unroll
            for (int i = 0; i < 8; i++) {
                ull a2 = bcast2(sA[kk][trow * 8 + i]);
#pragma unroll
                for (int j = 0; j < 4; j++) ffma2(acc2[i][j], a2, bv2[j]);
            }
        }
        __syncthreads();
    }
#pragma unroll
    for (int i = 0; i < 8; i++) {
        int m = m0 + trow * 8 + i;
#pragma unroll
        for (int j = 0; j < 4; j++) {
            int n = n0 + tcol * 8 + 2 * j;
            float2 v = *(float2*)&acc2[i][j];
            out[(size_t)m * NOUT + n] = v.x + by[n];
            out[(size_t)m * NOUT + n + 1] = v.y + by[n + 1];
        }
    }
}

// ---------------------------------------------------------------------------
// Softmax in-place over rows of 256. One warp per row.
// ---------------------------------------------------------------------------
__global__ void softmax_kernel(float* __restrict__ out) {
    int gwarp = (blockIdx.x * blockDim.x + threadIdx.x) >> 5;
    int lane = threadIdx.x & 31;
    float* row = out + (size_t)gwarp * NOUT;
    float v[8];
    float mx = -1e30f;
#pragma unroll
    for (int i = 0; i < 8; i++) {
        v[i] = row[i * 32 + lane];
        mx = fmaxf(mx, v[i]);
    }
#pragma unroll
    for (int o = 16; o; o >>= 1) mx = fmaxf(mx, __shfl_xor_sync(0xffffffffu, mx, o));
    float s = 0.f;
#pragma unroll
    for (int i = 0; i < 8; i++) {
        v[i] = expf(v[i] - mx);
        s += v[i];
    }
#pragma unroll
    for (int o = 16; o; o >>= 1) s += __shfl_xor_sync(0xffffffffu, s, o);
    float inv = 1.0f / s;
#pragma unroll
    for (int i = 0; i < 8; i++) row[i * 32 + lane] = v[i] * inv;
}

extern "C" void kernel_launch(void* const* d_in, const int* in_sizes, int n_in,
                              void* d_out, int out_size) {
    const float* u   = (const float*)d_in[0];
    const float* Wuh = (const float*)d_in[1];
    const float* Whh = (const float*)d_in[2];
    const float* Why = (const float*)d_in[3];
    const float* bh  = (const float*)d_in[4];
    const float* by  = (const float*)d_in[5];
    const float* h0  = (const float*)d_in[6];
    const float* tau = (const float*)d_in[7];
    float* out = (float*)d_out;

    const int smem_bytes = (256 * 128 + 64 * 260) * sizeof(float);  // 197632
    cudaFuncSetAttribute(recur_kernel, cudaFuncAttributeMaxDynamicSharedMemorySize,
                         smem_bytes);

    gemm1_kernel<<<dim3(256, 16), 256>>>(u, Wuh, bh);
    recur_kernel<<<NCTA, 256, smem_bytes>>>(Whh, tau, h0);
    gemm3_kernel<<<dim3(256, 2), 256>>>(Why, by, out);
    softmax_kernel<<<(BB * TT) / 8, 256>>>(out);
}

// round 12
// speedup vs baseline: 1.2449x; 1.2449x over previous
#include <cuda_runtime.h>
#include <cuda_bf16.h>
#include <math.h>
#include <stdint.h>

#define BB   64
#define TT   512
#define NIN  256
#define NH   2048
#define NOUT 256
#define NCTA 128   // 16 n-tiles x 8 k-splits, all co-resident
#define KS   8
#define NT   16

typedef unsigned long long ull;

// Scratch (device globals; no allocation anywhere)
__device__ float g_X[(size_t)BB * TT * NH];        // [b*T+t][NH]
__device__ float g_H[(size_t)(TT + 1) * BB * NH];  // [t][b][NH]
__device__ float g_P[(size_t)KS * BB * NH];        // [ks][b][NH]
__device__ unsigned g_bar_arrive = 0;
__device__ unsigned g_bar_release = 0;

// Packed fp32x2 helpers (gemm1/gemm3 issue relief)
__device__ __forceinline__ ull bcast2(float x) {
    ull r;
    asm("mov.b64 %0, {%1, %1};" : "=l"(r) : "f"(x));
    return r;
}
__device__ __forceinline__ void ffma2(ull& d, ull a, ull b) {
    asm("fma.rn.f32x2 %0, %1, %2, %0;" : "+l"(d) : "l"(a), "l"(b));
}

__device__ __forceinline__ uint32_t smem_u32(const void* p) {
    uint32_t a;
    asm("{ .reg .u64 t; cvta.to.shared.u64 t, %1; cvt.u32.u64 %0, t; }"
        : "=r"(a) : "l"(p));
    return a;
}

// Portable warp-level tensor ops (valid on base compute_103 target)
__device__ __forceinline__ void ldsm_x4(uint32_t& r0, uint32_t& r1, uint32_t& r2,
                                        uint32_t& r3, uint32_t addr) {
    asm volatile("ldmatrix.sync.aligned.m8n8.x4.shared.b16 {%0,%1,%2,%3}, [%4];"
                 : "=r"(r0), "=r"(r1), "=r"(r2), "=r"(r3) : "r"(addr));
}
__device__ __forceinline__ void ldsm_x2(uint32_t& r0, uint32_t& r1, uint32_t addr) {
    asm volatile("ldmatrix.sync.aligned.m8n8.x2.shared.b16 {%0,%1}, [%2];"
                 : "=r"(r0), "=r"(r1) : "r"(addr));
}
__device__ __forceinline__ void mma_bf16(float* d, const uint32_t* a,
                                         const uint32_t* b) {
    asm volatile(
        "mma.sync.aligned.m16n8k16.row.col.f32.bf16.bf16.f32 "
        "{%0,%1,%2,%3}, {%4,%5,%6,%7}, {%8,%9}, {%0,%1,%2,%3};"
        : "+f"(d[0]), "+f"(d[1]), "+f"(d[2]), "+f"(d[3])
        : "r"(a[0]), "r"(a[1]), "r"(a[2]), "r"(a[3]), "r"(b[0]), "r"(b[1]));
}

// ---------------------------------------------------------------------------
// GEMM1: g_X = u @ W_uh + b_h     (M=32768, K=256, N=2048), 128x128 tile
// ---------------------------------------------------------------------------
__global__ __launch_bounds__(256) void gemm1_kernel(const float* __restrict__ u,
                                                    const float* __restrict__ W,
                                                    const float* __restrict__ bias) {
    __shared__ float sA[16][129];
    __shared__ float sB[16][128];
    const int m0 = blockIdx.x * 128;
    const int n0 = blockIdx.y * 128;
    const int tid = threadIdx.x;
    const int tcol = tid & 15;
    const int trow = tid >> 4;
    ull acc2[8][4];
#pragma unroll
    for (int i = 0; i < 8; i++)
#pragma unroll
        for (int j = 0; j < 4; j++) acc2[i][j] = 0ull;

    for (int k0 = 0; k0 < NIN; k0 += 16) {
#pragma unroll
        for (int i = 0; i < 8; i++) {
            int idx = tid + i * 256;
            int m = idx >> 4, k = idx & 15;
            sA[k][m] = u[(size_t)(m0 + m) * NIN + k0 + k];
        }
#pragma unroll
        for (int i = 0; i < 8; i++) {
            int idx = tid + i * 256;
            int k = idx >> 7, n = idx & 127;
            sB[k][n] = W[(size_t)(k0 + k) * NH + n0 + n];
        }
        __syncthreads();
#pragma unroll
        for (int kk = 0; kk < 16; kk++) {
            const ulonglong2* bp = (const ulonglong2*)(&sB[kk][tcol * 8]);
            ulonglong2 B0 = bp[0], B1 = bp[1];
            ull bv2[4] = {B0.x, B0.y, B1.x, B1.y};
#pragma unroll
            for (int i = 0; i < 8; i++) {
                ull a2 = bcast2(sA[kk][trow * 8 + i]);
#pragma unroll
                for (int j = 0; j < 4; j++) ffma2(acc2[i][j], a2, bv2[j]);
            }
        }
        __syncthreads();
    }
#pragma unroll
    for (int i = 0; i < 8; i++) {
        int m = m0 + trow * 8 + i;
#pragma unroll
        for (int j = 0; j < 4; j++) {
            int n = n0 + tcol * 8 + 2 * j;
            float2 v = *(float2*)&acc2[i][j];
            g_X[(size_t)m * NH + n] = v.x + bias[n];
            g_X[(size_t)m * NH + n + 1] = v.y + bias[n + 1];
        }
    }
}

// ---------------------------------------------------------------------------
// Grid barrier (R9-proven: atomic arrive + monotonic release counter).
// ---------------------------------------------------------------------------
__device__ __forceinline__ void grid_bar(unsigned& gen) {
    __threadfence();
    __syncthreads();
    if (threadIdx.x == 0) {
        unsigned prev = atomicAdd(&g_bar_arrive, 1);
        if (prev == NCTA - 1) {
            g_bar_arrive = 0;
            __threadfence();
            atomicAdd(&g_bar_release, 1);
        } else {
            while (*((volatile unsigned*)&g_bar_release) == gen) { }
        }
        gen++;
    }
    __syncthreads();
}

// ---------------------------------------------------------------------------
// Persistent recurrence, warp-level bf16 MMA (hi+lo double-bf16).
// CTA (nt, ks): D[64b x 128n] partial over K-slice [kb, kb+256).
//  sW: W^T slice [128 n][256 k] bf16 hi+lo, resident all 512 steps.
//  sH: h_t slice [64 b][256 k] bf16 hi+lo, converted each step.
//  3 MMA segments: h_hi*W_hi + h_lo*W_hi + h_hi*W_lo (lo*lo dropped).
//  Warp w covers n in [w*16, w*16+16): 4 m16 tiles x 2 n8 tiles.
// Row stride 264 bf16 = 528 B (odd 16B multiple -> ldmatrix conflict-free).
// ---------------------------------------------------------------------------
#define KSTRIDE 264                       // bf16 elems per smem row
#define SW_HI 0
#define SW_LO (128 * KSTRIDE * 2)         // 67584
#define SH_HI (2 * 128 * KSTRIDE * 2)     // 135168
#define SH_LO (SH_HI + 64 * KSTRIDE * 2)  // 168960
#define SMEM_RECUR (SH_LO + 64 * KSTRIDE * 2)   // 202752

__global__ __launch_bounds__(256, 1) void recur_kernel(const float* __restrict__ Whh,
                                                       const float* __restrict__ tau,
                                                       const float* __restrict__ h0) {
    extern __shared__ char smem[];
    const uint32_t sbase = smem_u32(smem);

    const int tid = threadIdx.x;
    const int wid = tid >> 5;
    const int lane = tid & 31;
    const int cid = blockIdx.x;
    const int nt = cid & (NT - 1);
    const int ks = cid >> 4;
    const int n0 = nt * 128;
    const int kb = ks * 256;

    unsigned gen = 0;
    if (tid == 0) gen = *((volatile unsigned*)&g_bar_release);

    // ---- One-time: W slice -> sW[n][k] bf16 hi+lo (W^T, row n, k contig) ----
    for (int i = tid; i < 128 * 256; i += 256) {
        int n = i & 127, k = i >> 7;
        float w = Whh[(size_t)(kb + k) * NH + n0 + n];
        __nv_bfloat16 hi = __float2bfloat16(w);
        __nv_bfloat16 lo = __float2bfloat16(w - __bfloat162float(hi));
        *(__nv_bfloat16*)(smem + SW_HI + (n * KSTRIDE + k) * 2) = hi;
        *(__nv_bfloat16*)(smem + SW_LO + (n * KSTRIDE + k) * 2) = lo;
    }

    // Init g_H[0]: elems [cid*1024, cid*1024+1024)
    {
        int base = cid * 1024 + tid * 4;
        int j = base & (NH - 1);
        float4 v = *(const float4*)(h0 + j);
        v.x = fminf(1.f, fmaxf(-1.f, v.x));
        v.y = fminf(1.f, fmaxf(-1.f, v.y));
        v.z = fminf(1.f, fmaxf(-1.f, v.z));
        v.w = fminf(1.f, fmaxf(-1.f, v.w));
        *(float4*)(g_H + base) = v;
    }
    grid_bar(gen);

    // ldmatrix per-lane address components
    const uint32_t a_row = lane & 15;         // A: rows 0-15, halves by lane>>4
    const uint32_t a_half = (lane >> 4) * 16; // byte offset for k+8 tile
    const uint32_t b_row = lane & 7;          // B: rows 0-7, halves by bit3
    const uint32_t b_half = ((lane >> 3) & 1) * 16;

    // Phase-B constants
    float* __restrict__ Pp = g_P + (size_t)ks * BB * NH;
    const int fbase = cid * 1024 + tid * 4;
    const int fb = fbase >> 11;
    const int fj = fbase & (NH - 1);
    const float4 tv = *(const float4*)(tau + fj);
    float4 av4;
    av4.x = 1.0f / tv.x; av4.y = 1.0f / tv.y; av4.z = 1.0f / tv.z; av4.w = 1.0f / tv.w;

    for (int t = 0; t < TT; t++) {
        // ---- Convert h_t slice -> sH bf16 hi+lo ----
        const float* __restrict__ Ht = g_H + (size_t)t * BB * NH;
        for (int i = tid; i < 4096; i += 256) {      // 64 b x 64 k4
            int b = i >> 6, k4 = i & 63;
            float4 v = *(const float4*)(Ht + (size_t)b * NH + kb + k4 * 4);
            __nv_bfloat16 hx = __float2bfloat16(v.x);
            __nv_bfloat16 hy = __float2bfloat16(v.y);
            __nv_bfloat16 hz = __float2bfloat16(v.z);
            __nv_bfloat16 hw = __float2bfloat16(v.w);
            __nv_bfloat16 lx = __float2bfloat16(v.x - __bfloat162float(hx));
            __nv_bfloat16 ly = __float2bfloat16(v.y - __bfloat162float(hy));
            __nv_bfloat16 lz = __float2bfloat16(v.z - __bfloat162float(hz));
            __nv_bfloat16 lw = __float2bfloat16(v.w - __bfloat162float(hw));
            char* ph = smem + SH_HI + (b * KSTRIDE + k4 * 4) * 2;
            char* pl = smem + SH_LO + (b * KSTRIDE + k4 * 4) * 2;
            *(__nv_bfloat162*)(ph) = __halves2bfloat162(hx, hy);
            *(__nv_bfloat162*)(ph + 4) = __halves2bfloat162(hz, hw);
            *(__nv_bfloat162*)(pl) = __halves2bfloat162(lx, ly);
            *(__nv_bfloat162*)(pl + 4) = __halves2bfloat162(lz, lw);
        }
        __syncthreads();

        // ---- MMA: 3 segments x 16 k-steps; warp w -> n [w*16, w*16+16) ----
        float d[4][2][4];
#pragma unroll
        for (int mi = 0; mi < 4; mi++)
#pragma unroll
            for (int ni = 0; ni < 2; ni++)
#pragma unroll
                for (int r = 0; r < 4; r++) d[mi][ni][r] = 0.f;

#pragma unroll
        for (int seg = 0; seg < 3; seg++) {
            const uint32_t sh = sbase + ((seg == 1) ? SH_LO : SH_HI);
            const uint32_t sw = sbase + ((seg == 2) ? SW_LO : SW_HI);
#pragma unroll 2
            for (int kt = 0; kt < 16; kt++) {
                const uint32_t kbyte = kt * 32;   // 16 bf16 = 32 B
                uint32_t bfr[2][2];
#pragma unroll
                for (int ni = 0; ni < 2; ni++) {
                    uint32_t addr = sw + (wid * 16 + ni * 8 + b_row) * (KSTRIDE * 2)
                                    + kbyte + b_half;
                    ldsm_x2(bfr[ni][0], bfr[ni][1], addr);
                }
#pragma unroll
                for (int mi = 0; mi < 4; mi++) {
                    uint32_t afr[4];
                    uint32_t addr = sh + (mi * 16 + a_row) * (KSTRIDE * 2)
                                    + kbyte + a_half;
                    ldsm_x4(afr[0], afr[1], afr[2], afr[3], addr);
#pragma unroll
                    for (int ni = 0; ni < 2; ni++) mma_bf16(d[mi][ni], afr, bfr[ni]);
                }
            }
        }
        __syncthreads();   // before next-step convert overwrites sH

        // ---- Write partials: Pp[b][n0 + n] ----
#pragma unroll
        for (int mi = 0; mi < 4; mi++) {
#pragma unroll
            for (int ni = 0; ni < 2; ni++) {
                int r = mi * 16 + (lane >> 2);
                int c = n0 + wid * 16 + ni * 8 + (lane & 3) * 2;
                *(float2*)(Pp + (size_t)r * NH + c) = make_float2(d[mi][ni][0], d[mi][ni][1]);
                *(float2*)(Pp + (size_t)(r + 8) * NH + c) = make_float2(d[mi][ni][2], d[mi][ni][3]);
            }
        }
        grid_bar(gen);

        // ---- Phase B: fixed-order reduce over 8 splits + tanh update ----
        float4 pre = *(const float4*)(g_X + ((size_t)fb * TT + t) * NH + fj);
#pragma unroll
        for (int s = 0; s < KS; s++) {
            float4 p = __ldcg((const float4*)(g_P + (size_t)s * BB * NH + fbase));
            pre.x += p.x; pre.y += p.y; pre.z += p.z; pre.w += p.w;
        }
        float4 h = *(const float4*)(g_H + (size_t)t * BB * NH + fbase);
        float4 hn;
        hn.x = (1.0f - av4.x) * h.x + av4.x * tanhf(pre.x);
        hn.y = (1.0f - av4.y) * h.y + av4.y * tanhf(pre.y);
        hn.z = (1.0f - av4.z) * h.z + av4.z * tanhf(pre.z);
        hn.w = (1.0f - av4.w) * h.w + av4.w * tanhf(pre.w);
        *(float4*)(g_H + (size_t)(t + 1) * BB * NH + fbase) = hn;
        grid_bar(gen);
    }
}

// ---------------------------------------------------------------------------
// GEMM3: logits = H[t+1] @ W_hy + b_y  (M=32768, K=2048, N=256)
// ---------------------------------------------------------------------------
__global__ __launch_bounds__(256) void gemm3_kernel(const float* __restrict__ Why,
                                                    const float* __restrict__ by,
                                                    float* __restrict__ out) {
    __shared__ float sA[16][129];
    __shared__ float sB[16][128];
    const int m0 = blockIdx.x * 128;
    const int n0 = blockIdx.y * 128;
    const int tid = threadIdx.x;
    const int tcol = tid & 15;
    const int trow = tid >> 4;
    ull acc2[8][4];
#pragma unroll
    for (int i = 0; i < 8; i++)
#pragma unroll
        for (int j = 0; j < 4; j++) acc2[i][j] = 0ull;

    for (int k0 = 0; k0 < NH; k0 += 16) {
#pragma unroll
        for (int i = 0; i < 8; i++) {
            int idx = tid + i * 256;
            int m = idx >> 4, k = idx & 15;
            int gm = m0 + m;
            int b = gm >> 9;
            int tt = gm & (TT - 1);
            sA[k][m] = g_H[((size_t)(tt + 1) * BB + b) * NH + k0 + k];
        }
#pragma unroll
        for (int i = 0; i < 8; i++) {
            int idx = tid + i * 256;
            int k = idx >> 7, n = idx & 127;
            sB[k][n] = Why[(size_t)(k0 + k) * NOUT + n0 + n];
        }
        __syncthreads();
#pragma unroll
        for (int kk = 0; kk < 16; kk++) {
            const ulonglong2* bp = (const ulonglong2*)(&sB[kk][tcol * 8]);
            ulonglong2 B0 = bp[0], B1 = bp[1];
            ull bv2[4] = {B0.x, B0.y, B1.x, B1.y};
#pragma unroll
            for (int i = 0; i < 8; i++) {
                ull a2 = bcast2(sA[kk][trow * 8 + i]);
#pragma unroll
                for (int j = 0; j < 4; j++) ffma2(acc2[i][j], a2, bv2[j]);
            }
        }
        __syncthreads();
    }
#pragma unroll
    for (int i = 0; i < 8; i++) {
        int m = m0 + trow * 8 + i;
#pragma unroll
        for (int j = 0; j < 4; j++) {
            int n = n0 + tcol * 8 + 2 * j;
            float2 v = *(float2*)&acc2[i][j];
            out[(size_t)m * NOUT + n] = v.x + by[n];
            out[(size_t)m * NOUT + n + 1] = v.y + by[n + 1];
        }
    }
}

// ---------------------------------------------------------------------------
// Softmax in-place over rows of 256. One warp per row.
// ---------------------------------------------------------------------------
__global__ void softmax_kernel(float* __restrict__ out) {
    int gwarp = (blockIdx.x * blockDim.x + threadIdx.x) >> 5;
    int lane = threadIdx.x & 31;
    float* row = out + (size_t)gwarp * NOUT;
    float v[8];
    float mx = -1e30f;
#pragma unroll
    for (int i = 0; i < 8; i++) {
        v[i] = row[i * 32 + lane];
        mx = fmaxf(mx, v[i]);
    }
#pragma unroll
    for (int o = 16; o; o >>= 1) mx = fmaxf(mx, __shfl_xor_sync(0xffffffffu, mx, o));
    float s = 0.f;
#pragma unroll
    for (int i = 0; i < 8; i++) {
        v[i] = expf(v[i] - mx);
        s += v[i];
    }
#pragma unroll
    for (int o = 16; o; o >>= 1) s += __shfl_xor_sync(0xffffffffu, s, o);
    float inv = 1.0f / s;
#pragma unroll
    for (int i = 0; i < 8; i++) row[i * 32 + lane] = v[i] * inv;
}

extern "C" void kernel_launch(void* const* d_in, const int* in_sizes, int n_in,
                              void* d_out, int out_size) {
    const float* u   = (const float*)d_in[0];
    const float* Wuh = (const float*)d_in[1];
    const float* Whh = (const float*)d_in[2];
    const float* Why = (const float*)d_in[3];
    const float* bh  = (const float*)d_in[4];
    const float* by  = (const float*)d_in[5];
    const float* h0  = (const float*)d_in[6];
    const float* tau = (const float*)d_in[7];
    float* out = (float*)d_out;

    cudaFuncSetAttribute(recur_kernel, cudaFuncAttributeMaxDynamicSharedMemorySize,
                         SMEM_RECUR);

    gemm1_kernel<<<dim3(256, 16), 256>>>(u, Wuh, bh);
    recur_kernel<<<NCTA, 256, SMEM_RECUR>>>(Whh, tau, h0);
    gemm3_kernel<<<dim3(256, 2), 256>>>(Why, by, out);
    softmax_kernel<<<(BB * TT) / 8, 256>>>(out);
}

// round 13
// speedup vs baseline: 1.7840x; 1.4331x over previous
#include <cuda_runtime.h>
#include <cuda_bf16.h>
#include <math.h>
#include <stdint.h>

#define BB   64
#define TT   512
#define NIN  256
#define NH   2048
#define NOUT 256
#define NCTA 128   // 16 n-tiles x 8 k-splits, all co-resident
#define KS   8
#define NT   16

typedef unsigned long long ull;

// Scratch (device globals; no allocation anywhere)
__device__ float g_X[(size_t)BB * TT * NH];        // [b*T+t][NH]
__device__ float g_H[(size_t)(TT + 1) * BB * NH];  // [t][b][NH]
__device__ float g_P[(size_t)KS * BB * NH];        // [ks][b][NH]
__device__ __nv_bfloat16 g_Hhi[(size_t)BB * NH];   // current h, bf16 hi limb
__device__ __nv_bfloat16 g_Hlo[(size_t)BB * NH];   // current h, bf16 lo limb
__device__ unsigned g_bar_arrive = 0;
__device__ unsigned g_bar_release = 0;

// Packed fp32x2 helpers (gemm1/gemm3 issue relief)
__device__ __forceinline__ ull bcast2(float x) {
    ull r;
    asm("mov.b64 %0, {%1, %1};" : "=l"(r) : "f"(x));
    return r;
}
__device__ __forceinline__ void ffma2(ull& d, ull a, ull b) {
    asm("fma.rn.f32x2 %0, %1, %2, %0;" : "+l"(d) : "l"(a), "l"(b));
}

__device__ __forceinline__ uint32_t smem_u32(const void* p) {
    uint32_t a;
    asm("{ .reg .u64 t; cvta.to.shared.u64 t, %1; cvt.u32.u64 %0, t; }"
        : "=r"(a) : "l"(p));
    return a;
}

// Portable warp-level tensor ops (valid on base compute_103 target)
__device__ __forceinline__ void ldsm_x4(uint32_t& r0, uint32_t& r1, uint32_t& r2,
                                        uint32_t& r3, uint32_t addr) {
    asm volatile("ldmatrix.sync.aligned.m8n8.x4.shared.b16 {%0,%1,%2,%3}, [%4];"
                 : "=r"(r0), "=r"(r1), "=r"(r2), "=r"(r3) : "r"(addr));
}
__device__ __forceinline__ void ldsm_x2(uint32_t& r0, uint32_t& r1, uint32_t addr) {
    asm volatile("ldmatrix.sync.aligned.m8n8.x2.shared.b16 {%0,%1}, [%2];"
                 : "=r"(r0), "=r"(r1) : "r"(addr));
}
__device__ __forceinline__ void mma_bf16(float* d, const uint32_t* a,
                                         const uint32_t* b) {
    asm volatile(
        "mma.sync.aligned.m16n8k16.row.col.f32.bf16.bf16.f32 "
        "{%0,%1,%2,%3}, {%4,%5,%6,%7}, {%8,%9}, {%0,%1,%2,%3};"
        : "+f"(d[0]), "+f"(d[1]), "+f"(d[2]), "+f"(d[3])
        : "r"(a[0]), "r"(a[1]), "r"(a[2]), "r"(a[3]), "r"(b[0]), "r"(b[1]));
}

__device__ __forceinline__ uint4 ldcg4(const void* p) {
    uint4 v;
    asm volatile("ld.global.cg.v4.u32 {%0,%1,%2,%3}, [%4];"
                 : "=r"(v.x), "=r"(v.y), "=r"(v.z), "=r"(v.w) : "l"(p));
    return v;
}

// ---------------------------------------------------------------------------
// GEMM1: g_X = u @ W_uh + b_h     (M=32768, K=256, N=2048), 128x128 tile
// ---------------------------------------------------------------------------
__global__ __launch_bounds__(256) void gemm1_kernel(const float* __restrict__ u,
                                                    const float* __restrict__ W,
                                                    const float* __restrict__ bias) {
    __shared__ float sA[16][129];
    __shared__ float sB[16][128];
    const int m0 = blockIdx.x * 128;
    const int n0 = blockIdx.y * 128;
    const int tid = threadIdx.x;
    const int tcol = tid & 15;
    const int trow = tid >> 4;
    ull acc2[8][4];
#pragma unroll
    for (int i = 0; i < 8; i++)
#pragma unroll
        for (int j = 0; j < 4; j++) acc2[i][j] = 0ull;

    for (int k0 = 0; k0 < NIN; k0 += 16) {
#pragma unroll
        for (int i = 0; i < 8; i++) {
            int idx = tid + i * 256;
            int m = idx >> 4, k = idx & 15;
            sA[k][m] = u[(size_t)(m0 + m) * NIN + k0 + k];
        }
#pragma unroll
        for (int i = 0; i < 8; i++) {
            int idx = tid + i * 256;
            int k = idx >> 7, n = idx & 127;
            sB[k][n] = W[(size_t)(k0 + k) * NH + n0 + n];
        }
        __syncthreads();
#pragma unroll
        for (int kk = 0; kk < 16; kk++) {
            const ulonglong2* bp = (const ulonglong2*)(&sB[kk][tcol * 8]);
            ulonglong2 B0 = bp[0], B1 = bp[1];
            ull bv2[4] = {B0.x, B0.y, B1.x, B1.y};
#pragma unroll
            for (int i = 0; i < 8; i++) {
                ull a2 = bcast2(sA[kk][trow * 8 + i]);
#pragma unroll
                for (int j = 0; j < 4; j++) ffma2(acc2[i][j], a2, bv2[j]);
            }
        }
        __syncthreads();
    }
#pragma unroll
    for (int i = 0; i < 8; i++) {
        int m = m0 + trow * 8 + i;
#pragma unroll
        for (int j = 0; j < 4; j++) {
            int n = n0 + tcol * 8 + 2 * j;
            float2 v = *(float2*)&acc2[i][j];
            g_X[(size_t)m * NH + n] = v.x + bias[n];
            g_X[(size_t)m * NH + n + 1] = v.y + bias[n + 1];
        }
    }
}

// ---------------------------------------------------------------------------
// Grid barrier (R9-proven: atomic arrive + monotonic release counter).
// ---------------------------------------------------------------------------
__device__ __forceinline__ void grid_bar(unsigned& gen) {
    __threadfence();
    __syncthreads();
    if (threadIdx.x == 0) {
        unsigned prev = atomicAdd(&g_bar_arrive, 1);
        if (prev == NCTA - 1) {
            g_bar_arrive = 0;
            __threadfence();
            atomicAdd(&g_bar_release, 1);
        } else {
            while (*((volatile unsigned*)&g_bar_release) == gen) { }
        }
        gen++;
    }
    __syncthreads();
}

// ---------------------------------------------------------------------------
// Persistent recurrence, warp-level bf16 MMA (hi+lo double-bf16).
// CTA (nt, ks): D[64b x 128n] partial over K-slice [kb, kb+256).
//  sW: W^T slice [128 n][256 k] bf16 hi+lo, resident all 512 steps.
//  sH: h_t slice [64 b][256 k] bf16 hi+lo — PURE COPY from g_Hhi/g_Hlo
//      (the hi/lo split is produced once per element in phase B).
//  3 MMA segments: h_hi*W_hi + h_lo*W_hi + h_hi*W_lo (lo*lo dropped).
//  Warp w covers n in [w*16, w*16+16): 4 m16 tiles x 2 n8 tiles.
// Row stride 264 bf16 = 528 B (odd 16B multiple -> ldmatrix conflict-free).
// ---------------------------------------------------------------------------
#define KSTRIDE 264                       // bf16 elems per smem row
#define SW_HI 0
#define SW_LO (128 * KSTRIDE * 2)         // 67584
#define SH_HI (2 * 128 * KSTRIDE * 2)     // 135168
#define SH_LO (SH_HI + 64 * KSTRIDE * 2)  // 168960
#define SMEM_RECUR (SH_LO + 64 * KSTRIDE * 2)   // 202752

__global__ __launch_bounds__(256, 1) void recur_kernel(const float* __restrict__ Whh,
                                                       const float* __restrict__ tau,
                                                       const float* __restrict__ h0) {
    extern __shared__ char smem[];
    const uint32_t sbase = smem_u32(smem);

    const int tid = threadIdx.x;
    const int wid = tid >> 5;
    const int lane = tid & 31;
    const int cid = blockIdx.x;
    const int nt = cid & (NT - 1);
    const int ks = cid >> 4;
    const int n0 = nt * 128;
    const int kb = ks * 256;

    unsigned gen = 0;
    if (tid == 0) gen = *((volatile unsigned*)&g_bar_release);

    // ---- One-time: W slice -> sW[n][k] bf16 hi+lo (W^T, row n, k contig) ----
    for (int i = tid; i < 128 * 256; i += 256) {
        int n = i & 127, k = i >> 7;
        float w = Whh[(size_t)(kb + k) * NH + n0 + n];
        __nv_bfloat16 hi = __float2bfloat16(w);
        __nv_bfloat16 lo = __float2bfloat16(w - __bfloat162float(hi));
        *(__nv_bfloat16*)(smem + SW_HI + (n * KSTRIDE + k) * 2) = hi;
        *(__nv_bfloat16*)(smem + SW_LO + (n * KSTRIDE + k) * 2) = lo;
    }

    // Init g_H[0] + its bf16 hi/lo limbs: elems [cid*1024, cid*1024+1024)
    {
        int base = cid * 1024 + tid * 4;
        int j = base & (NH - 1);
        float4 v = *(const float4*)(h0 + j);
        v.x = fminf(1.f, fmaxf(-1.f, v.x));
        v.y = fminf(1.f, fmaxf(-1.f, v.y));
        v.z = fminf(1.f, fmaxf(-1.f, v.z));
        v.w = fminf(1.f, fmaxf(-1.f, v.w));
        *(float4*)(g_H + base) = v;
        __nv_bfloat16 hx = __float2bfloat16(v.x);
        __nv_bfloat16 hy = __float2bfloat16(v.y);
        __nv_bfloat16 hz = __float2bfloat16(v.z);
        __nv_bfloat16 hw = __float2bfloat16(v.w);
        *(__nv_bfloat162*)(g_Hhi + base) = __halves2bfloat162(hx, hy);
        *(__nv_bfloat162*)(g_Hhi + base + 2) = __halves2bfloat162(hz, hw);
        *(__nv_bfloat162*)(g_Hlo + base) =
            __halves2bfloat162(__float2bfloat16(v.x - __bfloat162float(hx)),
                               __float2bfloat16(v.y - __bfloat162float(hy)));
        *(__nv_bfloat162*)(g_Hlo + base + 2) =
            __halves2bfloat162(__float2bfloat16(v.z - __bfloat162float(hz)),
                               __float2bfloat16(v.w - __bfloat162float(hw)));
    }
    grid_bar(gen);

    // ldmatrix per-lane address components
    const uint32_t a_row = lane & 15;         // A: rows 0-15, halves by lane>>4
    const uint32_t a_half = (lane >> 4) * 16; // byte offset for k+8 tile
    const uint32_t b_row = lane & 7;          // B: rows 0-7, halves by bit3
    const uint32_t b_half = ((lane >> 3) & 1) * 16;

    // Phase-B constants
    float* __restrict__ Pp = g_P + (size_t)ks * BB * NH;
    const int fbase = cid * 1024 + tid * 4;
    const int fb = fbase >> 11;
    const int fj = fbase & (NH - 1);
    const float4 tv = *(const float4*)(tau + fj);
    float4 av4;
    av4.x = 1.0f / tv.x; av4.y = 1.0f / tv.y; av4.z = 1.0f / tv.z; av4.w = 1.0f / tv.w;

    for (int t = 0; t < TT; t++) {
        // ---- Fill sH: pure 16B copies of the k-slice (no conversion math).
        // Same addresses every step -> must bypass L1 (__ldcg); producer
        // writes are ordered by the barriers around phase B.
        {
            const char* srchi = (const char*)g_Hhi;
            const char* srclo = (const char*)g_Hlo;
            for (int i = tid; i < 4096; i += 256) {      // 2 arrays x 64 b x 32 uint4
                int arr = i >> 11;                       // 0 = hi, 1 = lo
                int b = (i >> 5) & 63;
                int q = i & 31;                          // uint4 index within row
                const char* src = (arr ? srclo : srchi) +
                                  ((size_t)b * NH + kb) * 2 + q * 16;
                uint4 v = ldcg4(src);
                *(uint4*)(smem + (arr ? SH_LO : SH_HI) +
                          (b * KSTRIDE) * 2 + q * 16) = v;
            }
        }
        __syncthreads();

        // ---- MMA: 3 segments x 16 k-steps; warp w -> n [w*16, w*16+16) ----
        float d[4][2][4];
#pragma unroll
        for (int mi = 0; mi < 4; mi++)
#pragma unroll
            for (int ni = 0; ni < 2; ni++)
#pragma unroll
                for (int r = 0; r < 4; r++) d[mi][ni][r] = 0.f;

#pragma unroll
        for (int seg = 0; seg < 3; seg++) {
            const uint32_t sh = sbase + ((seg == 1) ? SH_LO : SH_HI);
            const uint32_t sw = sbase + ((seg == 2) ? SW_LO : SW_HI);
#pragma unroll 2
            for (int kt = 0; kt < 16; kt++) {
                const uint32_t kbyte = kt * 32;   // 16 bf16 = 32 B
                uint32_t bfr[2][2];
#pragma unroll
                for (int ni = 0; ni < 2; ni++) {
                    uint32_t addr = sw + (wid * 16 + ni * 8 + b_row) * (KSTRIDE * 2)
                                    + kbyte + b_half;
                    ldsm_x2(bfr[ni][0], bfr[ni][1], addr);
                }
#pragma unroll
                for (int mi = 0; mi < 4; mi++) {
                    uint32_t afr[4];
                    uint32_t addr = sh + (mi * 16 + a_row) * (KSTRIDE * 2)
                                    + kbyte + a_half;
                    ldsm_x4(afr[0], afr[1], afr[2], afr[3], addr);
#pragma unroll
                    for (int ni = 0; ni < 2; ni++) mma_bf16(d[mi][ni], afr, bfr[ni]);
                }
            }
        }
        __syncthreads();   // before next-step fill overwrites sH

        // ---- Write partials: Pp[b][n0 + n] ----
#pragma unroll
        for (int mi = 0; mi < 4; mi++) {
#pragma unroll
            for (int ni = 0; ni < 2; ni++) {
                int r = mi * 16 + (lane >> 2);
                int c = n0 + wid * 16 + ni * 8 + (lane & 3) * 2;
                *(float2*)(Pp + (size_t)r * NH + c) = make_float2(d[mi][ni][0], d[mi][ni][1]);
                *(float2*)(Pp + (size_t)(r + 8) * NH + c) = make_float2(d[mi][ni][2], d[mi][ni][3]);
            }
        }
        grid_bar(gen);

        // ---- Phase B: fixed-order reduce over 8 splits + tanh update,
        //      emitting fp32 h (for gemm3) AND its bf16 hi/lo limbs. ----
        float4 pre = *(const float4*)(g_X + ((size_t)fb * TT + t) * NH + fj);
#pragma unroll
        for (int s = 0; s < KS; s++) {
            float4 p = __ldcg((const float4*)(g_P + (size_t)s * BB * NH + fbase));
            pre.x += p.x; pre.y += p.y; pre.z += p.z; pre.w += p.w;
        }
        float4 h = *(const float4*)(g_H + (size_t)t * BB * NH + fbase);
        float4 hn;
        hn.x = (1.0f - av4.x) * h.x + av4.x * tanhf(pre.x);
        hn.y = (1.0f - av4.y) * h.y + av4.y * tanhf(pre.y);
        hn.z = (1.0f - av4.z) * h.z + av4.z * tanhf(pre.z);
        hn.w = (1.0f - av4.w) * h.w + av4.w * tanhf(pre.w);
        *(float4*)(g_H + (size_t)(t + 1) * BB * NH + fbase) = hn;
        {
            __nv_bfloat16 hx = __float2bfloat16(hn.x);
            __nv_bfloat16 hy = __float2bfloat16(hn.y);
            __nv_bfloat16 hz = __float2bfloat16(hn.z);
            __nv_bfloat16 hw = __float2bfloat16(hn.w);
            *(__nv_bfloat162*)(g_Hhi + fbase) = __halves2bfloat162(hx, hy);
            *(__nv_bfloat162*)(g_Hhi + fbase + 2) = __halves2bfloat162(hz, hw);
            *(__nv_bfloat162*)(g_Hlo + fbase) =
                __halves2bfloat162(__float2bfloat16(hn.x - __bfloat162float(hx)),
                                   __float2bfloat16(hn.y - __bfloat162float(hy)));
            *(__nv_bfloat162*)(g_Hlo + fbase + 2) =
                __halves2bfloat162(__float2bfloat16(hn.z - __bfloat162float(hz)),
                                   __float2bfloat16(hn.w - __bfloat162float(hw)));
        }
        grid_bar(gen);
    }
}

// ---------------------------------------------------------------------------
// GEMM3: logits = H[t+1] @ W_hy + b_y  (M=32768, K=2048, N=256)
// ---------------------------------------------------------------------------
__global__ __launch_bounds__(256) void gemm3_kernel(const float* __restrict__ Why,
                                                    const float* __restrict__ by,
                                                    float* __restrict__ out) {
    __shared__ float sA[16][129];
    __shared__ float sB[16][128];
    const int m0 = blockIdx.x * 128;
    const int n0 = blockIdx.y * 128;
    const int tid = threadIdx.x;
    const int tcol = tid & 15;
    const int trow = tid >> 4;
    ull acc2[8][4];
#pragma unroll
    for (int i = 0; i < 8; i++)
#pragma unroll
        for (int j = 0; j < 4; j++) acc2[i][j] = 0ull;

    for (int k0 = 0; k0 < NH; k0 += 16) {
#pragma unroll
        for (int i = 0; i < 8; i++) {
            int idx = tid + i * 256;
            int m = idx >> 4, k = idx & 15;
            int gm = m0 + m;
            int b = gm >> 9;
            int tt = gm & (TT - 1);
            sA[k][m] = g_H[((size_t)(tt + 1) * BB + b) * NH + k0 + k];
        }
#pragma unroll
        for (int i = 0; i < 8; i++) {
            int idx = tid + i * 256;
            int k = idx >> 7, n = idx & 127;
            sB[k][n] = Why[(size_t)(k0 + k) * NOUT + n0 + n];
        }
        __syncthreads();
#pragma unroll
        for (int kk = 0; kk < 16; kk++) {
            const ulonglong2* bp = (const ulonglong2*)(&sB[kk][tcol * 8]);
            ulonglong2 B0 = bp[0], B1 = bp[1];
            ull bv2[4] = {B0.x, B0.y, B1.x, B1.y};
#pragma unroll
            for (int i = 0; i < 8; i++) {
                ull a2 = bcast2(sA[kk][trow * 8 + i]);
#pragma unroll
                for (int j = 0; j < 4; j++) ffma2(acc2[i][j], a2, bv2[j]);
            }
        }
        __syncthreads();
    }
#pragma unroll
    for (int i = 0; i < 8; i++) {
        int m = m0 + trow * 8 + i;
#pragma unroll
        for (int j = 0; j < 4; j++) {
            int n = n0 + tcol * 8 + 2 * j;
            float2 v = *(float2*)&acc2[i][j];
            out[(size_t)m * NOUT + n] = v.x + by[n];
            out[(size_t)m * NOUT + n + 1] = v.y + by[n + 1];
        }
    }
}

// ---------------------------------------------------------------------------
// Softmax in-place over rows of 256. One warp per row.
// ---------------------------------------------------------------------------
__global__ void softmax_kernel(float* __restrict__ out) {
    int gwarp = (blockIdx.x * blockDim.x + threadIdx.x) >> 5;
    int lane = threadIdx.x & 31;
    float* row = out + (size_t)gwarp * NOUT;
    float v[8];
    float mx = -1e30f;
#pragma unroll
    for (int i = 0; i < 8; i++) {
        v[i] = row[i * 32 + lane];
        mx = fmaxf(mx, v[i]);
    }
#pragma unroll
    for (int o = 16; o; o >>= 1) mx = fmaxf(mx, __shfl_xor_sync(0xffffffffu, mx, o));
    float s = 0.f;
#pragma unroll
    for (int i = 0; i < 8; i++) {
        v[i] = expf(v[i] - mx);
        s += v[i];
    }
#pragma unroll
    for (int o = 16; o; o >>= 1) s += __shfl_xor_sync(0xffffffffu, s, o);
    float inv = 1.0f / s;
#pragma unroll
    for (int i = 0; i < 8; i++) row[i * 32 + lane] = v[i] * inv;
}

extern "C" void kernel_launch(void* const* d_in, const int* in_sizes, int n_in,
                              void* d_out, int out_size) {
    const float* u   = (const float*)d_in[0];
    const float* Wuh = (const float*)d_in[1];
    const float* Whh = (const float*)d_in[2];
    const float* Why = (const float*)d_in[3];
    const float* bh  = (const float*)d_in[4];
    const float* by  = (const float*)d_in[5];
    const float* h0  = (const float*)d_in[6];
    const float* tau = (const float*)d_in[7];
    float* out = (float*)d_out;

    cudaFuncSetAttribute(recur_kernel, cudaFuncAttributeMaxDynamicSharedMemorySize,
                         SMEM_RECUR);

    gemm1_kernel<<<dim3(256, 16), 256>>>(u, Wuh, bh);
    recur_kernel<<<NCTA, 256, SMEM_RECUR>>>(Whh, tau, h0);
    gemm3_kernel<<<dim3(256, 2), 256>>>(Why, by, out);
    softmax_kernel<<<(BB * TT) / 8, 256>>>(out);
}

// round 17
// speedup vs baseline: 2.1847x; 1.2246x over previous
#include <cuda_runtime.h>
#include <cuda_bf16.h>
#include <math.h>
#include <stdint.h>

#define BB   64
#define TT   512
#define NIN  256
#define NH   2048
#define NOUT 256
#define NCTA 128   // 16 n-tiles x 8 k-splits, all co-resident
#define KS   8
#define NT   16

typedef unsigned long long ull;

// Scratch (device globals; no allocation anywhere)
__device__ float g_X[(size_t)BB * TT * NH];        // [b*T+t][NH]
__device__ float g_H[(size_t)(TT + 1) * BB * NH];  // [t][b][NH]
__device__ float g_P[(size_t)KS * BB * NH];        // [ks][b][NH]
__device__ __nv_bfloat16 g_Hhi[(size_t)BB * NH];   // current h, bf16 hi limb
__device__ __nv_bfloat16 g_Hlo[(size_t)BB * NH];   // current h, bf16 lo limb
__device__ volatile unsigned g_flags[NCTA];        // flag barrier arrival slots
__device__ volatile unsigned g_rel;                // flag barrier release word

__device__ __forceinline__ uint32_t smem_u32(const void* p) {
    uint32_t a;
    asm("{ .reg .u64 t; cvta.to.shared.u64 t, %1; cvt.u32.u64 %0, t; }"
        : "=r"(a) : "l"(p));
    return a;
}

// Portable warp-level tensor ops (valid on base compute_103 target)
__device__ __forceinline__ void ldsm_x4(uint32_t& r0, uint32_t& r1, uint32_t& r2,
                                        uint32_t& r3, uint32_t addr) {
    asm volatile("ldmatrix.sync.aligned.m8n8.x4.shared.b16 {%0,%1,%2,%3}, [%4];"
                 : "=r"(r0), "=r"(r1), "=r"(r2), "=r"(r3) : "r"(addr));
}
__device__ __forceinline__ void ldsm_x2(uint32_t& r0, uint32_t& r1, uint32_t addr) {
    asm volatile("ldmatrix.sync.aligned.m8n8.x2.shared.b16 {%0,%1}, [%2];"
                 : "=r"(r0), "=r"(r1) : "r"(addr));
}
__device__ __forceinline__ void mma_bf16(float* d, const uint32_t* a,
                                         const uint32_t* b) {
    asm volatile(
        "mma.sync.aligned.m16n8k16.row.col.f32.bf16.bf16.f32 "
        "{%0,%1,%2,%3}, {%4,%5,%6,%7}, {%8,%9}, {%0,%1,%2,%3};"
        : "+f"(d[0]), "+f"(d[1]), "+f"(d[2]), "+f"(d[3])
        : "r"(a[0]), "r"(a[1]), "r"(a[2]), "r"(a[3]), "r"(b[0]), "r"(b[1]));
}

__device__ __forceinline__ uint4 ldcg4(const void* p) {
    uint4 v;
    asm volatile("ld.global.cg.v4.u32 {%0,%1,%2,%3}, [%4];"
                 : "=r"(v.x), "=r"(v.y), "=r"(v.z), "=r"(v.w) : "l"(p));
    return v;
}

// ---------------------------------------------------------------------------
// Flag-based grid barrier (R10-proven correctness): per-CTA arrival slots
// (parallel stores, no same-address atomic serialization), CTA 0 gathers
// with 128 parallel spinners, releases via one word. gen is per-thread,
// monotonic, seeded from g_rel at kernel start (replay-safe, no reset).
// ---------------------------------------------------------------------------
__device__ __forceinline__ void grid_bar(unsigned& gen, int cid, int tid) {
    gen++;
    __syncthreads();
    __threadfence();
    if (tid == 0) g_flags[cid] = gen;
    if (cid == 0) {
        if (tid < NCTA) {
            while (g_flags[tid] < gen) { }
        }
        __syncthreads();
        if (tid == 0) {
            __threadfence();
            g_rel = gen;
        }
    }
    if (tid == 0) {
        while (g_rel < gen) { }
    }
    __syncthreads();
}

// ---------------------------------------------------------------------------
// Tensorized GEMM (shared skeleton for gemm1/gemm3):
// CTA computes D[128m x 256n] over K in 128-chunks, double-bf16 3 segments
// (A_hi*B_hi + A_lo*B_hi + A_hi*B_lo), fp32 accum in registers.
// smem rows padded to 136 bf16 (272 B = odd multiple of 16 B).
// ---------------------------------------------------------------------------
#define GST 136
#define GA_HI 0
#define GA_LO (128 * GST * 2)             // 34816
#define GB_HI (2 * 128 * GST * 2)         // 69632
#define GB_LO (GB_HI + 256 * GST * 2)     // 139264
#define SMEM_GEMM (GB_LO + 256 * GST * 2) // 208896

// GEMM1: g_X = u @ W_uh + b_h  (M=32768, K=256, N=2048). grid (256, 8).
__global__ __launch_bounds__(256, 1) void gemm1_tc(const float* __restrict__ u,
                                                   const float* __restrict__ W,
                                                   const float* __restrict__ bias) {
    extern __shared__ char smem[];
    const uint32_t sbase = smem_u32(smem);
    const int tid = threadIdx.x;
    const int wid = tid >> 5;
    const int lane = tid & 31;
    const int m0 = blockIdx.x * 128;
    const int n0 = blockIdx.y * 256;

    const uint32_t a_row = lane & 15;
    const uint32_t a_half = (lane >> 4) * 16;
    const uint32_t b_row = lane & 7;
    const uint32_t b_half = ((lane >> 3) & 1) * 16;

    float d[8][4][4];
#pragma unroll
    for (int mt = 0; mt < 8; mt++)
#pragma unroll
        for (int nt4 = 0; nt4 < 4; nt4++)
#pragma unroll
            for (int r = 0; r < 4; r++) d[mt][nt4][r] = 0.f;

    for (int kc = 0; kc < NIN / 128; kc++) {
        __syncthreads();
        // Fill A (u rows) hi/lo
        for (int i = tid; i < 128 * 32; i += 256) {
            int m = i >> 5, k4 = i & 31;
            float4 v = *(const float4*)(u + (size_t)(m0 + m) * NIN + kc * 128 + k4 * 4);
            __nv_bfloat16 hx = __float2bfloat16(v.x);
            __nv_bfloat16 hy = __float2bfloat16(v.y);
            __nv_bfloat16 hz = __float2bfloat16(v.z);
            __nv_bfloat16 hw = __float2bfloat16(v.w);
            char* ph = smem + GA_HI + (m * GST + k4 * 4) * 2;
            char* pl = smem + GA_LO + (m * GST + k4 * 4) * 2;
            *(__nv_bfloat162*)(ph) = __halves2bfloat162(hx, hy);
            *(__nv_bfloat162*)(ph + 4) = __halves2bfloat162(hz, hw);
            *(__nv_bfloat162*)(pl) =
                __halves2bfloat162(__float2bfloat16(v.x - __bfloat162float(hx)),
                                   __float2bfloat16(v.y - __bfloat162float(hy)));
            *(__nv_bfloat162*)(pl + 4) =
                __halves2bfloat162(__float2bfloat16(v.z - __bfloat162float(hz)),
                                   __float2bfloat16(v.w - __bfloat162float(hw)));
        }
        // Fill B (W^T rows n, k contig) hi/lo
        for (int i = tid; i < 256 * 128; i += 256) {
            int n = i & 255, k = i >> 8;
            float w = W[(size_t)(kc * 128 + k) * NH + n0 + n];
            __nv_bfloat16 hi = __float2bfloat16(w);
            __nv_bfloat16 lo = __float2bfloat16(w - __bfloat162float(hi));
            *(__nv_bfloat16*)(smem + GB_HI + (n * GST + k) * 2) = hi;
            *(__nv_bfloat16*)(smem + GB_LO + (n * GST + k) * 2) = lo;
        }
        __syncthreads();

#pragma unroll
        for (int seg = 0; seg < 3; seg++) {
            const uint32_t sa = sbase + ((seg == 1) ? GA_LO : GA_HI);
            const uint32_t sb = sbase + ((seg == 2) ? GB_LO : GB_HI);
#pragma unroll 2
            for (int kt = 0; kt < 8; kt++) {
                const uint32_t kbyte = kt * 32;
                uint32_t bfr[4][2];
#pragma unroll
                for (int nt4 = 0; nt4 < 4; nt4++) {
                    uint32_t addr = sb + (wid * 32 + nt4 * 8 + b_row) * (GST * 2)
                                    + kbyte + b_half;
                    ldsm_x2(bfr[nt4][0], bfr[nt4][1], addr);
                }
#pragma unroll
                for (int mt = 0; mt < 8; mt++) {
                    uint32_t afr[4];
                    uint32_t addr = sa + (mt * 16 + a_row) * (GST * 2)
                                    + kbyte + a_half;
                    ldsm_x4(afr[0], afr[1], afr[2], afr[3], addr);
#pragma unroll
                    for (int nt4 = 0; nt4 < 4; nt4++) mma_bf16(d[mt][nt4], afr, bfr[nt4]);
                }
            }
        }
    }

#pragma unroll
    for (int mt = 0; mt < 8; mt++) {
#pragma unroll
        for (int nt4 = 0; nt4 < 4; nt4++) {
            int r = mt * 16 + (lane >> 2);
            int c = n0 + wid * 32 + nt4 * 8 + (lane & 3) * 2;
            float b0 = bias[c], b1 = bias[c + 1];
            *(float2*)(g_X + (size_t)(m0 + r) * NH + c) =
                make_float2(d[mt][nt4][0] + b0, d[mt][nt4][1] + b1);
            *(float2*)(g_X + (size_t)(m0 + r + 8) * NH + c) =
                make_float2(d[mt][nt4][2] + b0, d[mt][nt4][3] + b1);
        }
    }
}

// GEMM3: out = H[t+1] @ W_hy + b_y  (M=32768, K=2048, N=256). grid (256).
__global__ __launch_bounds__(256, 1) void gemm3_tc(const float* __restrict__ Why,
                                                   const float* __restrict__ by,
                                                   float* __restrict__ out) {
    extern __shared__ char smem[];
    const uint32_t sbase = smem_u32(smem);
    const int tid = threadIdx.x;
    const int wid = tid >> 5;
    const int lane = tid & 31;
    const int m0 = blockIdx.x * 128;

    const uint32_t a_row = lane & 15;
    const uint32_t a_half = (lane >> 4) * 16;
    const uint32_t b_row = lane & 7;
    const uint32_t b_half = ((lane >> 3) & 1) * 16;

    float d[8][4][4];
#pragma unroll
    for (int mt = 0; mt < 8; mt++)
#pragma unroll
        for (int nt4 = 0; nt4 < 4; nt4++)
#pragma unroll
            for (int r = 0; r < 4; r++) d[mt][nt4][r] = 0.f;

    for (int kc = 0; kc < NH / 128; kc++) {
        __syncthreads();
        // Fill A (H rows, m = b*T + t) hi/lo
        for (int i = tid; i < 128 * 32; i += 256) {
            int m = i >> 5, k4 = i & 31;
            int gm = m0 + m;
            int b = gm >> 9;
            int tt = gm & (TT - 1);
            float4 v = *(const float4*)(g_H + ((size_t)(tt + 1) * BB + b) * NH
                                        + kc * 128 + k4 * 4);
            __nv_bfloat16 hx = __float2bfloat16(v.x);
            __nv_bfloat16 hy = __float2bfloat16(v.y);
            __nv_bfloat16 hz = __float2bfloat16(v.z);
            __nv_bfloat16 hw = __float2bfloat16(v.w);
            char* ph = smem + GA_HI + (m * GST + k4 * 4) * 2;
            char* pl = smem + GA_LO + (m * GST + k4 * 4) * 2;
            *(__nv_bfloat162*)(ph) = __halves2bfloat162(hx, hy);
            *(__nv_bfloat162*)(ph + 4) = __halves2bfloat162(hz, hw);
            *(__nv_bfloat162*)(pl) =
                __halves2bfloat162(__float2bfloat16(v.x - __bfloat162float(hx)),
                                   __float2bfloat16(v.y - __bfloat162float(hy)));
            *(__nv_bfloat162*)(pl + 4) =
                __halves2bfloat162(__float2bfloat16(v.z - __bfloat162float(hz)),
                                   __float2bfloat16(v.w - __bfloat162float(hw)));
        }
        // Fill B (W_hy^T rows n, k contig) hi/lo
        for (int i = tid; i < 256 * 128; i += 256) {
            int n = i & 255, k = i >> 8;
            float w = Why[(size_t)(kc * 128 + k) * NOUT + n];
            __nv_bfloat16 hi = __float2bfloat16(w);
            __nv_bfloat16 lo = __float2bfloat16(w - __bfloat162float(hi));
            *(__nv_bfloat16*)(smem + GB_HI + (n * GST + k) * 2) = hi;
            *(__nv_bfloat16*)(smem + GB_LO + (n * GST + k) * 2) = lo;
        }
        __syncthreads();

#pragma unroll
        for (int seg = 0; seg < 3; seg++) {
            const uint32_t sa = sbase + ((seg == 1) ? GA_LO : GA_HI);
            const uint32_t sb = sbase + ((seg == 2) ? GB_LO : GB_HI);
#pragma unroll 2
            for (int kt = 0; kt < 8; kt++) {
                const uint32_t kbyte = kt * 32;
                uint32_t bfr[4][2];
#pragma unroll
                for (int nt4 = 0; nt4 < 4; nt4++) {
                    uint32_t addr = sb + (wid * 32 + nt4 * 8 + b_row) * (GST * 2)
                                    + kbyte + b_half;
                    ldsm_x2(bfr[nt4][0], bfr[nt4][1], addr);
                }
#pragma unroll
                for (int mt = 0; mt < 8; mt++) {
                    uint32_t afr[4];
                    uint32_t addr = sa + (mt * 16 + a_row) * (GST * 2)
                                    + kbyte + a_half;
                    ldsm_x4(afr[0], afr[1], afr[2], afr[3], addr);
#pragma unroll
                    for (int nt4 = 0; nt4 < 4; nt4++) mma_bf16(d[mt][nt4], afr, bfr[nt4]);
                }
            }
        }
    }

#pragma unroll
    for (int mt = 0; mt < 8; mt++) {
#pragma unroll
        for (int nt4 = 0; nt4 < 4; nt4++) {
            int r = mt * 16 + (lane >> 2);
            int c = wid * 32 + nt4 * 8 + (lane & 3) * 2;
            float b0 = by[c], b1 = by[c + 1];
            *(float2*)(out + (size_t)(m0 + r) * NOUT + c) =
                make_float2(d[mt][nt4][0] + b0, d[mt][nt4][1] + b1);
            *(float2*)(out + (size_t)(m0 + r + 8) * NOUT + c) =
                make_float2(d[mt][nt4][2] + b0, d[mt][nt4][3] + b1);
        }
    }
}

// ---------------------------------------------------------------------------
// Persistent recurrence — R13 body verbatim (global per-step barriers,
// precomputed bf16 limbs, single-buffered), with the flag barrier swapped in.
// ---------------------------------------------------------------------------
#define KSTRIDE 264                       // bf16 elems per smem row
#define SW_HI 0
#define SW_LO (128 * KSTRIDE * 2)         // 67584
#define SH_HI (2 * 128 * KSTRIDE * 2)     // 135168
#define SH_LO (SH_HI + 64 * KSTRIDE * 2)  // 168960
#define SMEM_RECUR (SH_LO + 64 * KSTRIDE * 2)   // 202752

__global__ __launch_bounds__(256, 1) void recur_kernel(const float* __restrict__ Whh,
                                                       const float* __restrict__ tau,
                                                       const float* __restrict__ h0) {
    extern __shared__ char smem[];
    const uint32_t sbase = smem_u32(smem);

    const int tid = threadIdx.x;
    const int wid = tid >> 5;
    const int lane = tid & 31;
    const int cid = blockIdx.x;
    const int nt = cid & (NT - 1);
    const int ks = cid >> 4;
    const int n0 = nt * 128;
    const int kb = ks * 256;

    unsigned gen = g_rel;   // monotonic, replay-safe seed (same for all threads)

    // ---- One-time: W slice -> sW[n][k] bf16 hi+lo (W^T, row n, k contig) ----
    for (int i = tid; i < 128 * 256; i += 256) {
        int n = i & 127, k = i >> 7;
        float w = Whh[(size_t)(kb + k) * NH + n0 + n];
        __nv_bfloat16 hi = __float2bfloat16(w);
        __nv_bfloat16 lo = __float2bfloat16(w - __bfloat162float(hi));
        *(__nv_bfloat16*)(smem + SW_HI + (n * KSTRIDE + k) * 2) = hi;
        *(__nv_bfloat16*)(smem + SW_LO + (n * KSTRIDE + k) * 2) = lo;
    }

    // Init g_H[0] + its bf16 hi/lo limbs: elems [cid*1024, cid*1024+1024)
    {
        int base = cid * 1024 + tid * 4;
        int j = base & (NH - 1);
        float4 v = *(const float4*)(h0 + j);
        v.x = fminf(1.f, fmaxf(-1.f, v.x));
        v.y = fminf(1.f, fmaxf(-1.f, v.y));
        v.z = fminf(1.f, fmaxf(-1.f, v.z));
        v.w = fminf(1.f, fmaxf(-1.f, v.w));
        *(float4*)(g_H + base) = v;
        __nv_bfloat16 hx = __float2bfloat16(v.x);
        __nv_bfloat16 hy = __float2bfloat16(v.y);
        __nv_bfloat16 hz = __float2bfloat16(v.z);
        __nv_bfloat16 hw = __float2bfloat16(v.w);
        *(__nv_bfloat162*)(g_Hhi + base) = __halves2bfloat162(hx, hy);
        *(__nv_bfloat162*)(g_Hhi + base + 2) = __halves2bfloat162(hz, hw);
        *(__nv_bfloat162*)(g_Hlo + base) =
            __halves2bfloat162(__float2bfloat16(v.x - __bfloat162float(hx)),
                               __float2bfloat16(v.y - __bfloat162float(hy)));
        *(__nv_bfloat162*)(g_Hlo + base + 2) =
            __halves2bfloat162(__float2bfloat16(v.z - __bfloat162float(hz)),
                               __float2bfloat16(v.w - __bfloat162float(hw)));
    }
    grid_bar(gen, cid, tid);

    // ldmatrix per-lane address components
    const uint32_t a_row = lane & 15;
    const uint32_t a_half = (lane >> 4) * 16;
    const uint32_t b_row = lane & 7;
    const uint32_t b_half = ((lane >> 3) & 1) * 16;

    // Phase-B constants
    float* __restrict__ Pp = g_P + (size_t)ks * BB * NH;
    const int fbase = cid * 1024 + tid * 4;
    const int fb = fbase >> 11;
    const int fj = fbase & (NH - 1);
    const float4 tv = *(const float4*)(tau + fj);
    float4 av4;
    av4.x = 1.0f / tv.x; av4.y = 1.0f / tv.y; av4.z = 1.0f / tv.z; av4.w = 1.0f / tv.w;

    for (int t = 0; t < TT; t++) {
        // ---- Fill sH: pure 16B copies of the k-slice (no conversion math) ----
        {
            const char* srchi = (const char*)g_Hhi;
            const char* srclo = (const char*)g_Hlo;
            for (int i = tid; i < 4096; i += 256) {      // 2 arrays x 64 b x 32 uint4
                int arr = i >> 11;
                int b = (i >> 5) & 63;
                int q = i & 31;
                const char* src = (arr ? srclo : srchi) +
                                  ((size_t)b * NH + kb) * 2 + q * 16;
                uint4 v = ldcg4(src);
                *(uint4*)(smem + (arr ? SH_LO : SH_HI) +
                          (b * KSTRIDE) * 2 + q * 16) = v;
            }
        }
        __syncthreads();

        // ---- MMA: 3 segments x 16 k-steps; warp w -> n [w*16, w*16+16) ----
        float d[4][2][4];
#pragma unroll
        for (int mi = 0; mi < 4; mi++)
#pragma unroll
            for (int ni = 0; ni < 2; ni++)
#pragma unroll
                for (int r = 0; r < 4; r++) d[mi][ni][r] = 0.f;

#pragma unroll
        for (int seg = 0; seg < 3; seg++) {
            const uint32_t sh = sbase + ((seg == 1) ? SH_LO : SH_HI);
            const uint32_t sw = sbase + ((seg == 2) ? SW_LO : SW_HI);
#pragma unroll 2
            for (int kt = 0; kt < 16; kt++) {
                const uint32_t kbyte = kt * 32;
                uint32_t bfr[2][2];
#pragma unroll
                for (int ni = 0; ni < 2; ni++) {
                    uint32_t addr = sw + (wid * 16 + ni * 8 + b_row) * (KSTRIDE * 2)
                                    + kbyte + b_half;
                    ldsm_x2(bfr[ni][0], bfr[ni][1], addr);
                }
#pragma unroll
                for (int mi = 0; mi < 4; mi++) {
                    uint32_t afr[4];
                    uint32_t addr = sh + (mi * 16 + a_row) * (KSTRIDE * 2)
                                    + kbyte + a_half;
                    ldsm_x4(afr[0], afr[1], afr[2], afr[3], addr);
#pragma unroll
                    for (int ni = 0; ni < 2; ni++) mma_bf16(d[mi][ni], afr, bfr[ni]);
                }
            }
        }
        __syncthreads();   // before next-step fill overwrites sH

        // ---- Write partials: Pp[b][n0 + n] ----
#pragma unroll
        for (int mi = 0; mi < 4; mi++) {
#pragma unroll
            for (int ni = 0; ni < 2; ni++) {
                int r = mi * 16 + (lane >> 2);
                int c = n0 + wid * 16 + ni * 8 + (lane & 3) * 2;
                *(float2*)(Pp + (size_t)r * NH + c) = make_float2(d[mi][ni][0], d[mi][ni][1]);
                *(float2*)(Pp + (size_t)(r + 8) * NH + c) = make_float2(d[mi][ni][2], d[mi][ni][3]);
            }
        }
        grid_bar(gen, cid, tid);

        // ---- Phase B: fixed-order reduce over 8 splits + tanh update,
        //      emitting fp32 h (for gemm3) AND its bf16 hi/lo limbs. ----
        float4 pre = *(const float4*)(g_X + ((size_t)fb * TT + t) * NH + fj);
#pragma unroll
        for (int s = 0; s < KS; s++) {
            float4 p = __ldcg((const float4*)(g_P + (size_t)s * BB * NH + fbase));
            pre.x += p.x; pre.y += p.y; pre.z += p.z; pre.w += p.w;
        }
        float4 h = *(const float4*)(g_H + (size_t)t * BB * NH + fbase);
        float4 hn;
        hn.x = (1.0f - av4.x) * h.x + av4.x * tanhf(pre.x);
        hn.y = (1.0f - av4.y) * h.y + av4.y * tanhf(pre.y);
        hn.z = (1.0f - av4.z) * h.z + av4.z * tanhf(pre.z);
        hn.w = (1.0f - av4.w) * h.w + av4.w * tanhf(pre.w);
        *(float4*)(g_H + (size_t)(t + 1) * BB * NH + fbase) = hn;
        {
            __nv_bfloat16 hx = __float2bfloat16(hn.x);
            __nv_bfloat16 hy = __float2bfloat16(hn.y);
            __nv_bfloat16 hz = __float2bfloat16(hn.z);
            __nv_bfloat16 hw = __float2bfloat16(hn.w);
            *(__nv_bfloat162*)(g_Hhi + fbase) = __halves2bfloat162(hx, hy);
            *(__nv_bfloat162*)(g_Hhi + fbase + 2) = __halves2bfloat162(hz, hw);
            *(__nv_bfloat162*)(g_Hlo + fbase) =
                __halves2bfloat162(__float2bfloat16(hn.x - __bfloat162float(hx)),
                                   __float2bfloat16(hn.y - __bfloat162float(hy)));
            *(__nv_bfloat162*)(g_Hlo + fbase + 2) =
                __halves2bfloat162(__float2bfloat16(hn.z - __bfloat162float(hz)),
                                   __float2bfloat16(hn.w - __bfloat162float(hw)));
        }
        grid_bar(gen, cid, tid);
    }
}

// ---------------------------------------------------------------------------
// Softmax in-place over rows of 256. One warp per row.
// ---------------------------------------------------------------------------
__global__ void softmax_kernel(float* __restrict__ out) {
    int gwarp = (blockIdx.x * blockDim.x + threadIdx.x) >> 5;
    int lane = threadIdx.x & 31;
    float* row = out + (size_t)gwarp * NOUT;
    float v[8];
    float mx = -1e30f;
#pragma unroll
    for (int i = 0; i < 8; i++) {
        v[i] = row[i * 32 + lane];
        mx = fmaxf(mx, v[i]);
    }
#pragma unroll
    for (int o = 16; o; o >>= 1) mx = fmaxf(mx, __shfl_xor_sync(0xffffffffu, mx, o));
    float s = 0.f;
#pragma unroll
    for (int i = 0; i < 8; i++) {
        v[i] = expf(v[i] - mx);
        s += v[i];
    }
#pragma unroll
    for (int o = 16; o; o >>= 1) s += __shfl_xor_sync(0xffffffffu, s, o);
    float inv = 1.0f / s;
#pragma unroll
    for (int i = 0; i < 8; i++) row[i * 32 + lane] = v[i] * inv;
}

extern "C" void kernel_launch(void* const* d_in, const int* in_sizes, int n_in,
                              void* d_out, int out_size) {
    const float* u   = (const float*)d_in[0];
    const float* Wuh = (const float*)d_in[1];
    const float* Whh = (const float*)d_in[2];
    const float* Why = (const float*)d_in[3];
    const float* bh  = (const float*)d_in[4];
    const float* by  = (const float*)d_in[5];
    const float* h0  = (const float*)d_in[6];
    const float* tau = (const float*)d_in[7];
    float* out = (float*)d_out;

    cudaFuncSetAttribute(recur_kernel, cudaFuncAttributeMaxDynamicSharedMemorySize,
                         SMEM_RECUR);
    cudaFuncSetAttribute(gemm1_tc, cudaFuncAttributeMaxDynamicSharedMemorySize,
                         SMEM_GEMM);
    cudaFuncSetAttribute(gemm3_tc, cudaFuncAttributeMaxDynamicSharedMemorySize,
                         SMEM_GEMM);

    gemm1_tc<<<dim3(256, 8), 256, SMEM_GEMM>>>(u, Wuh, bh);
    recur_kernel<<<NCTA, 256, SMEM_RECUR>>>(Whh, tau, h0);
    gemm3_tc<<<256, 256, SMEM_GEMM>>>(Why, by, out);
    softmax_kernel<<<(BB * TT) / 8, 256>>>(out);
}